// round 2
// baseline (speedup 1.0000x reference)
#include <cuda_runtime.h>
#include <cstdint>

// SparseMixer top-1 forward (N rows, E=64 experts, fp32).
// Per row: mlt=max, sel=argmax (first-index tie-break);
//   keep j iff !( (mlt-l_j)/max(|l_j|,mlt) > 0.2 )   (NaN ratio -> keep)
//   denom = sum_kept exp(l_j - mlt)
//   multiplier_o = exp(l_sel - mlt)/denom = 1/denom   (l_sel == mlt exactly)
//   mask_for_one = (sel == argmax(masked)) || rand_u > 0.75 ? 1.0 : 0.3333
// Outputs (f32): sel (as float), multiplier = mask_for_one/denom, loss = 0.
//
// Layout: one HALF-WARP (16 lanes) per row; each lane loads float4
// (16 x 16B = 256B row, LDG.128 fully coalesced). Butterfly reductions with
// xor offsets {8,4,2,1} stay inside the 16-lane group.

__global__ __launch_bounds__(256) void sparsemixer_kernel(
    const float* __restrict__ logits,
    const float* __restrict__ rand_u,
    float* __restrict__ out_sel,    // may be null
    float* __restrict__ out_mult,
    float* __restrict__ out_loss,   // may be null
    int n_rows)
{
    const int tid   = blockIdx.x * blockDim.x + threadIdx.x;
    const int row   = tid >> 4;           // half-warp id == row
    const int sub   = threadIdx.x & 15;   // lane within 16-lane group
    if (row >= n_rows) return;

    // ---- load 4 contiguous floats: 16 lanes x float4 = 256B row ----
    const float4 v = *reinterpret_cast<const float4*>(
        logits + (size_t)row * 64 + sub * 4);

    // ---- local (max, argmax), first-index tie-break ----
    const int base = sub * 4;
    float m = v.x; int idx = base;
    if (v.y > m) { m = v.y; idx = base + 1; }
    if (v.z > m) { m = v.z; idx = base + 2; }
    if (v.w > m) { m = v.w; idx = base + 3; }

    #pragma unroll
    for (int off = 8; off > 0; off >>= 1) {
        float om = __shfl_xor_sync(0xFFFFFFFFu, m, off);
        int   oi = __shfl_xor_sync(0xFFFFFFFFu, idx, off);
        if (om > m || (om == m && oi < idx)) { m = om; idx = oi; }
    }
    const float mlt = m;
    const int   sel = idx;

    // ---- mask + partial exp-sum, all in registers ----
    const float r0 = (mlt - v.x) / fmaxf(fabsf(v.x), mlt);
    const float r1 = (mlt - v.y) / fmaxf(fabsf(v.y), mlt);
    const float r2 = (mlt - v.z) / fmaxf(fabsf(v.z), mlt);
    const float r3 = (mlt - v.w) / fmaxf(fabsf(v.w), mlt);
    const bool k0 = !(r0 > 0.2f);
    const bool k1 = !(r1 > 0.2f);
    const bool k2 = !(r2 > 0.2f);
    const bool k3 = !(r3 > 0.2f);

    float s = (k0 ? __expf(v.x - mlt) : 0.0f)
            + (k1 ? __expf(v.y - mlt) : 0.0f)
            + (k2 ? __expf(v.z - mlt) : 0.0f)
            + (k3 ? __expf(v.w - mlt) : 0.0f);

    // ---- masked argmax (first-index tie-break) ----
    const float NEG_INF = __int_as_float(0xff800000);
    float mm = k0 ? v.x : NEG_INF; int midx = base;
    const float m1 = k1 ? v.y : NEG_INF;
    const float m2 = k2 ? v.z : NEG_INF;
    const float m3 = k3 ? v.w : NEG_INF;
    if (m1 > mm) { mm = m1; midx = base + 1; }
    if (m2 > mm) { mm = m2; midx = base + 2; }
    if (m3 > mm) { mm = m3; midx = base + 3; }

    // ---- fused reduction: denom sum + masked argmax ----
    #pragma unroll
    for (int off = 8; off > 0; off >>= 1) {
        s += __shfl_xor_sync(0xFFFFFFFFu, s, off);
        float om = __shfl_xor_sync(0xFFFFFFFFu, mm, off);
        int   oi = __shfl_xor_sync(0xFFFFFFFFu, midx, off);
        if (om > mm || (om == mm && oi < midx)) { mm = om; midx = oi; }
    }

    if (sub == 0) {
        const float ru = rand_u[row];
        const bool  b  = (sel == midx) || (ru > 0.75f);
        const float mfo = b ? 1.0f : 0.3333f;     // 0.3333 + 0.6667*b
        if (out_sel)  out_sel[row] = (float)sel;
        out_mult[row] = mfo / s;
        if (out_loss && row == 0) *out_loss = 0.0f;
    }
}

extern "C" void kernel_launch(void* const* d_in, const int* in_sizes, int n_in,
                              void* d_out, int out_size)
{
    const float* logits = (const float*)d_in[0];
    const float* rand_u = (const float*)d_in[1];
    float* out = (float*)d_out;

    const int n_rows = in_sizes[0] / 64;

    // Output layout (f32), defensively chosen from out_size:
    //   2N+1 : [sel(N), mult(N), loss(1)]
    //   2N   : [sel(N), mult(N)]
    //   N    : [mult(N)] only
    float* o_sel  = nullptr;
    float* o_mult = out;
    float* o_loss = nullptr;
    if (out_size >= 2 * n_rows) {
        o_sel  = out;
        o_mult = out + n_rows;
        if (out_size > 2 * n_rows) o_loss = out + 2 * n_rows;
    }

    const int threads = 256;                    // 16 rows per block
    const int rows_per_block = threads / 16;
    const int blocks = (n_rows + rows_per_block - 1) / rows_per_block;

    sparsemixer_kernel<<<blocks, threads>>>(logits, rand_u,
                                            o_sel, o_mult, o_loss, n_rows);
}

// round 5
// speedup vs baseline: 1.3934x; 1.3934x over previous
#include <cuda_runtime.h>
#include <cstdint>

// SparseMixer top-1 forward (N rows, E=64, fp32).
// Identity: argmax(masked_gates) == sel always (the argmax element has ratio 0,
// survives the mask, and first-index tie-break order is preserved), so
// mask_for_one == 1.0 and rand_u is irrelevant.
// Outputs (f32): sel, multiplier = 1/denom, loss = 0, where
// denom = sum_{kept j} exp(l_j - mlt), kept = !((mlt-l_j)/max(|l_j|,mlt) > 0.2).
//
// One half-warp (16 lanes) per row, float4 loads (LDG.128, 256B/row coalesced).
// Butterfly 1: max only. Butterfly 2: fused (first-index min, fp32 sum).
// Plain __shfl_xor_sync only (matches the toolchain path that already passed).

__global__ __launch_bounds__(256) void sparsemixer_kernel(
    const float* __restrict__ logits,
    float* __restrict__ out_sel,    // may be null
    float* __restrict__ out_mult,
    float* __restrict__ out_loss,   // may be null
    int n_rows)
{
    const int tid  = blockIdx.x * blockDim.x + threadIdx.x;
    const int row  = tid >> 4;
    const int sub  = threadIdx.x & 15;
    if (row >= n_rows) return;

    // ---- load row: 16 lanes x float4 = 256B, fully coalesced ----
    const float4 v = *reinterpret_cast<const float4*>(
        logits + (size_t)row * 64 + sub * 4);

    // ---- local max over 4 elements (value only) ----
    const float m01 = fmaxf(v.x, v.y);
    const float m23 = fmaxf(v.z, v.w);
    float m = fmaxf(m01, m23);

    // ---- butterfly 1: group max (4 steps, xor offsets stay in 16-lane group) ----
    float mlt = m;
    #pragma unroll
    for (int off = 8; off > 0; off >>= 1)
        mlt = fmaxf(mlt, __shfl_xor_sync(0xFFFFFFFFu, mlt, off));

    // ---- local first index attaining mlt (first-index tie-break) ----
    const int base = sub * 4;
    int cand = 64;
    if (v.w == mlt) cand = base + 3;
    if (v.z == mlt) cand = base + 2;
    if (v.y == mlt) cand = base + 1;
    if (v.x == mlt) cand = base;

    // ---- mask (IEEE div, matches XLA rounding) + exp partial sum ----
    const float r0 = (mlt - v.x) / fmaxf(fabsf(v.x), mlt);
    const float r1 = (mlt - v.y) / fmaxf(fabsf(v.y), mlt);
    const float r2 = (mlt - v.z) / fmaxf(fabsf(v.z), mlt);
    const float r3 = (mlt - v.w) / fmaxf(fabsf(v.w), mlt);

    float s = (!(r0 > 0.2f) ? __expf(v.x - mlt) : 0.0f)
            + (!(r1 > 0.2f) ? __expf(v.y - mlt) : 0.0f)
            + (!(r2 > 0.2f) ? __expf(v.z - mlt) : 0.0f)
            + (!(r3 > 0.2f) ? __expf(v.w - mlt) : 0.0f);

    // ---- butterfly 2 (fused): first-index min + fp32 sum ----
    #pragma unroll
    for (int off = 8; off > 0; off >>= 1) {
        const int   oc = __shfl_xor_sync(0xFFFFFFFFu, cand, off);
        const float os = __shfl_xor_sync(0xFFFFFFFFu, s,   off);
        cand = min(cand, oc);
        s   += os;
    }

    if (sub == 0) {
        if (out_sel) out_sel[row] = (float)cand;
        out_mult[row] = 1.0f / s;    // mask_for_one == 1.0 identically
        if (out_loss && row == 0) *out_loss = 0.0f;
    }
}

extern "C" void kernel_launch(void* const* d_in, const int* in_sizes, int n_in,
                              void* d_out, int out_size)
{
    const float* logits = (const float*)d_in[0];
    float* out = (float*)d_out;

    const int n_rows = in_sizes[0] / 64;

    // Output layout (f32): [sel(N), mult(N), loss(1)] (defensive on out_size)
    float* o_sel  = nullptr;
    float* o_mult = out;
    float* o_loss = nullptr;
    if (out_size >= 2 * n_rows) {
        o_sel  = out;
        o_mult = out + n_rows;
        if (out_size > 2 * n_rows) o_loss = out + 2 * n_rows;
    }

    const int threads = 256;                    // 16 rows per block
    const int rows_per_block = threads / 16;
    const int blocks = (n_rows + rows_per_block - 1) / rows_per_block;

    sparsemixer_kernel<<<blocks, threads>>>(logits, o_sel, o_mult, o_loss, n_rows);
}

// round 6
// speedup vs baseline: 2.4286x; 1.7429x over previous
#include <cuda_runtime.h>
#include <cstdint>

// SparseMixer top-1 forward (N rows, E=64, fp32).
// Identity (validated R5, rel_err 2.3e-8): argmax(masked_gates) == sel always,
// so mask_for_one == 1.0 and rand_u is irrelevant.
// Outputs (f32): sel, multiplier = 1/denom, loss = 0, where
//   denom = sum_{kept j} exp(l_j - mlt),
//   kept  = !( RN((mlt-l_j)/max(|l_j|,mlt)) > 0.2f )   (NaN -> keep).
//
// Div-free mask: sign of q = fma(-0.2, d, num) decides; disagreement with the
// IEEE-div predicate is only possible when |q| < ~4e-9*d, so lanes with
// min|q| < 2e-6 (rare) recompute their 8 masks exactly via __fdiv_rn.
//
// Layout: 8 lanes per row, 8 elements/lane via two float4 loads. Each LDG.128
// covers 4 rows x 128B = 4 full cache lines (fully coalesced). Butterflies are
// 3 steps (xor 4,2,1), staying inside the 8-lane group.

__global__ __launch_bounds__(256) void sparsemixer_kernel(
    const float* __restrict__ logits,
    float* __restrict__ out_sel,    // may be null
    float* __restrict__ out_mult,
    float* __restrict__ out_loss,   // may be null
    int n_rows)
{
    const int tid = blockIdx.x * blockDim.x + threadIdx.x;
    const int row = tid >> 3;
    const int sub = threadIdx.x & 7;
    if (row >= n_rows) return;

    const float* rp = logits + (size_t)row * 64;
    const float4 a = *reinterpret_cast<const float4*>(rp + sub * 4);
    const float4 b = *reinterpret_cast<const float4*>(rp + 32 + sub * 4);
    float va[8] = {a.x, a.y, a.z, a.w, b.x, b.y, b.z, b.w};

    // ---- local max (7 FMNMX) + 3-step group max ----
    float m = va[0];
    #pragma unroll
    for (int j = 1; j < 8; j++) m = fmaxf(m, va[j]);
    float mlt = m;
    #pragma unroll
    for (int off = 4; off > 0; off >>= 1)
        mlt = fmaxf(mlt, __shfl_xor_sync(0xFFFFFFFFu, mlt, off));

    // ---- first column attaining mlt (this lane); cols ascend with j ----
    int cand = 64;
    #pragma unroll
    for (int j = 7; j >= 0; j--)
        if (va[j] == mlt) cand = (j < 4) ? (sub * 4 + j) : (32 + sub * 4 + j - 4);

    // ---- div-free mask + exp partial sum ----
    float nums[8], ds[8];
    bool  msk[8];
    float minq = 1e30f;
    #pragma unroll
    for (int j = 0; j < 8; j++) {
        const float num = mlt - va[j];
        const float d   = fmaxf(fabsf(va[j]), mlt);
        const float q   = fmaf(-0.2f, d, num);
        msk[j] = (q > 0.0f);                 // NaN q -> false -> keep (matches ref)
        minq   = fminf(minq, fabsf(q));      // NaN |q| ignored by fminf -> exact
        nums[j] = num; ds[j] = d;            //   NaN path also gives keep: OK
    }
    if (minq < 2e-6f) {                      // ~1e-6 probability: exact refinement
        #pragma unroll
        for (int j = 0; j < 8; j++)
            msk[j] = (__fdiv_rn(nums[j], ds[j]) > 0.2f);
    }
    float s = 0.0f;
    #pragma unroll
    for (int j = 0; j < 8; j++)
        s += msk[j] ? 0.0f : __expf(-nums[j]);   // exp(l - mlt) == exp(-num)

    // ---- fused 3-step butterfly: fp32 sum + first-index min ----
    #pragma unroll
    for (int off = 4; off > 0; off >>= 1) {
        s    += __shfl_xor_sync(0xFFFFFFFFu, s, off);
        cand  = min(cand, __shfl_xor_sync(0xFFFFFFFFu, cand, off));
    }

    if (sub == 0) {
        if (out_sel) out_sel[row] = (float)cand;
        out_mult[row] = 1.0f / s;            // mask_for_one == 1.0 identically
        if (out_loss && row == 0) *out_loss = 0.0f;
    }
}

extern "C" void kernel_launch(void* const* d_in, const int* in_sizes, int n_in,
                              void* d_out, int out_size)
{
    const float* logits = (const float*)d_in[0];
    float* out = (float*)d_out;

    const int n_rows = in_sizes[0] / 64;

    // Output layout (f32): [sel(N), mult(N), loss(1)] (defensive on out_size)
    float* o_sel  = nullptr;
    float* o_mult = out;
    float* o_loss = nullptr;
    if (out_size >= 2 * n_rows) {
        o_sel  = out;
        o_mult = out + n_rows;
        if (out_size > 2 * n_rows) o_loss = out + 2 * n_rows;
    }

    const int threads = 256;                   // 32 rows per block
    const int rows_per_block = threads / 8;
    const int blocks = (n_rows + rows_per_block - 1) / rows_per_block;

    sparsemixer_kernel<<<blocks, threads>>>(logits, o_sel, o_mult, o_loss, n_rows);
}